// round 12
// baseline (speedup 1.0000x reference)
#include <cuda_runtime.h>
#include <cuda_fp16.h>
#include <cstdint>

#define MAXN 8192
#define HD 64
#define SLOTS 32
#define EMB_MAX (50000 * HD)
#define BLKS 296
#define WPB 8
#define TW (BLKS * WPB)

// ---------------- static device scratch ----------------
__device__ __half g_embh[EMB_MAX];
__device__ float g_xe[MAXN * HD];
__device__ float g_h[MAXN * HD];
__device__ int g_wr[MAXN];
__device__ int g_cnt[MAXN];
__device__ int g_buck[MAXN * SLOTS];
__device__ volatile int g_ready[MAXN];
__device__ unsigned g_max[HD];
__device__ unsigned g_done;

// ---------------- prep: fp16 embedding conversion + state reset ----------------
__global__ void prep_kernel(const float* __restrict__ emb, const int* __restrict__ tree,
                            int n_steps, int emb_total) {
    int t = blockIdx.x * blockDim.x + threadIdx.x;
    int e = t * 8;
    if (e + 7 < emb_total) {
        float4 f0 = *reinterpret_cast<const float4*>(emb + e);
        float4 f1 = *reinterpret_cast<const float4*>(emb + e + 4);
        *reinterpret_cast<__half2*>(g_embh + e)     = __floats2half2_rn(f0.x, f0.y);
        *reinterpret_cast<__half2*>(g_embh + e + 2) = __floats2half2_rn(f0.z, f0.w);
        *reinterpret_cast<__half2*>(g_embh + e + 4) = __floats2half2_rn(f1.x, f1.y);
        *reinterpret_cast<__half2*>(g_embh + e + 6) = __floats2half2_rn(f1.z, f1.w);
    }
    if (t < n_steps) {
        g_wr[t] = tree[2 * t + 1];
        g_ready[t] = 0;
    }
    if (t < MAXN) g_cnt[t] = 0;
    if (t < HD) g_max[t] = 0u;
    if (t == 0) g_done = 0u;
}

// ---------------- bucket fill: writes per node ----------------
__global__ void fill_kernel(const int* __restrict__ tree, int n_steps) {
    int i = blockIdx.x * blockDim.x + threadIdx.x;
    if (i >= n_steps) return;
    int v = tree[2 * i + 1];
    int s = atomicAdd(&g_cnt[v], 1);
    if (s < SLOTS) g_buck[v * SLOTS + s] = i;
}

// ---------------- kernel A: pure gather at high occupancy (1 warp = 1 step) ----------------
__global__ void __launch_bounds__(256)
gatherA_kernel(const float* __restrict__ xw, const int* __restrict__ xi,
               int L, int n_steps) {
    int wid = threadIdx.x >> 5, l = threadIdx.x & 31;
    int i = blockIdx.x * WPB + wid;
    if (i >= n_steps) return;
    int rl = l & 7, rg = l >> 3;

    float acc[8] = {0.f, 0.f, 0.f, 0.f, 0.f, 0.f, 0.f, 0.f};
    const float* xwr = xw + (size_t)i * L;
    const int* xir = xi + (size_t)i * L;
#pragma unroll 2
    for (int r = 0; r < L; r += 16) {
        int rbase = r + 4 * rg;
        float4 w4 = __ldg(reinterpret_cast<const float4*>(xwr + rbase));
        int4 i4 = __ldg(reinterpret_cast<const int4*>(xir + rbase));
        uint4 u0 = __ldg(reinterpret_cast<const uint4*>(g_embh + (size_t)i4.x * HD + rl * 8));
        uint4 u1 = __ldg(reinterpret_cast<const uint4*>(g_embh + (size_t)i4.y * HD + rl * 8));
        uint4 u2 = __ldg(reinterpret_cast<const uint4*>(g_embh + (size_t)i4.z * HD + rl * 8));
        uint4 u3 = __ldg(reinterpret_cast<const uint4*>(g_embh + (size_t)i4.w * HD + rl * 8));
#define ACCUM(U, W)                                                              \
        {                                                                        \
            float2 f0 = __half22float2(*reinterpret_cast<__half2*>(&U.x));      \
            float2 f1 = __half22float2(*reinterpret_cast<__half2*>(&U.y));      \
            float2 f2 = __half22float2(*reinterpret_cast<__half2*>(&U.z));      \
            float2 f3 = __half22float2(*reinterpret_cast<__half2*>(&U.w));      \
            acc[0] = fmaf(W, f0.x, acc[0]); acc[1] = fmaf(W, f0.y, acc[1]);     \
            acc[2] = fmaf(W, f1.x, acc[2]); acc[3] = fmaf(W, f1.y, acc[3]);     \
            acc[4] = fmaf(W, f2.x, acc[4]); acc[5] = fmaf(W, f2.y, acc[5]);     \
            acc[6] = fmaf(W, f3.x, acc[6]); acc[7] = fmaf(W, f3.y, acc[7]);     \
        }
        ACCUM(u0, w4.x) ACCUM(u1, w4.y) ACCUM(u2, w4.z) ACCUM(u3, w4.w)
#undef ACCUM
    }
    // reduce over the 4 rg groups (same order as round-6 for bit-exactness)
#pragma unroll
    for (int u = 0; u < 8; u++) {
        acc[u] += __shfl_xor_sync(0xffffffffu, acc[u], 8);
        acc[u] += __shfl_xor_sync(0xffffffffu, acc[u], 16);
    }
    if (rg == 0) {
        float4 a = make_float4(acc[0], acc[1], acc[2], acc[3]);
        float4 b = make_float4(acc[4], acc[5], acc[6], acc[7]);
        *reinterpret_cast<float4*>(g_xe + (size_t)i * HD + rl * 8) = a;
        *reinterpret_cast<float4*>(g_xe + (size_t)i * HD + rl * 8 + 4) = b;
    }
}

// ---------------- kernel B: GRU recurrence dataflow (one step per warp) ----------------
__global__ void __launch_bounds__(256, 2)
recurB_kernel(const int* __restrict__ tree,
              const float* __restrict__ Wz, const float* __restrict__ Uz,
              const float* __restrict__ bz,
              const float* __restrict__ Wr, const float* __restrict__ Ur,
              const float* __restrict__ br,
              const float* __restrict__ Wh, const float* __restrict__ Uh,
              const float* __restrict__ bh,
              const int* __restrict__ np_ptr, int n_steps,
              float* __restrict__ out) {
    extern __shared__ float sm[];
    float* sWzr = sm;             // [k*128 + 4l + {Wz2l,Wz2l+1,Wr2l,Wr2l+1}]
    float* sWh2 = sm + 8192;
    float* sUzr = sm + 12288;
    float* sUh2 = sm + 20480;
    float* sXe = sm + 24576;      // per-warp 64
    float* sP  = sm + 25088;
    float* sPr = sm + 25600;

    int tid = threadIdx.x;
    int wid = tid >> 5, l = tid & 31;

    for (int t = tid; t < 8192; t += 256) {
        int k = t >> 7, q = t & 127, lane = q >> 2, c = q & 3;
        int j = 2 * lane + (c & 1);
        sWzr[t] = (c < 2 ? Wz : Wr)[j * 64 + k];
        sUzr[t] = (c < 2 ? Uz : Ur)[j * 64 + k];
    }
    for (int t = tid; t < 4096; t += 256) {
        int kp = t >> 7, q = t & 127, lane = q >> 2, c = q & 3;
        int j = 2 * lane + (c & 1);
        int k = 2 * kp + (c >> 1);
        sWh2[t] = Wh[j * 64 + k];
        sUh2[t] = Uh[j * 64 + k];
    }
    float2 bz2 = reinterpret_cast<const float2*>(bz)[l];
    float2 br2 = reinterpret_cast<const float2*>(br)[l];
    float2 bh2 = reinterpret_cast<const float2*>(bh)[l];
    int np1 = np_ptr[0] - 1;
    __syncthreads();

    const float4* Wzr4 = reinterpret_cast<const float4*>(sWzr);
    const float4* Wh4  = reinterpret_cast<const float4*>(sWh2);
    const float4* Uzr4 = reinterpret_cast<const float4*>(sUzr);
    const float4* Uh4  = reinterpret_cast<const float4*>(sUh2);
    float* xe_w = sXe + wid * 64;
    float* p_w  = sP + wid * 64;
    float* pr_w = sPr + wid * 64;
    float2 lm = make_float2(-3.402823466e38f, -3.402823466e38f);

    for (int i = blockIdx.x * WPB + wid; i < n_steps; i += TW) {
        // ---- load xe (computed by kernel A) ----
        float2 xe2 = __ldg(reinterpret_cast<const float2*>(g_xe + (size_t)i * HD) + l);
        *reinterpret_cast<float2*>(&xe_w[2 * l]) = xe2;
        __syncwarp();

        // ---- dep(i): last j<i writing node tree[i,0] ----
        int v = tree[2 * i];
        int c = g_cnt[v];
        int d = -1;
        if (c <= SLOTS) {
            if (l < c) {
                int j = g_buck[v * SLOTS + l];
                if (j < i) d = j;
            }
        } else {
            if (l == 0)
                for (int j = i - 1; j >= 0; --j)
                    if (g_wr[j] == v) { d = j; break; }
        }
        d = __reduce_max_sync(0xffffffffu, d);

        // ---- W matvecs (pre-wait): a = W xe + b ----
        float4 wzrA = make_float4(bz2.x, bz2.y, br2.x, br2.y);
        float4 wzrB = make_float4(0.f, 0.f, 0.f, 0.f);
        float2 whA = bh2, whB = make_float2(0.f, 0.f);
#pragma unroll
        for (int k = 0; k < 64; k += 2) {
            float2 x = *reinterpret_cast<const float2*>(&xe_w[k]);
            float4 m0 = Wzr4[k * 32 + l];
            float4 m1 = Wzr4[(k + 1) * 32 + l];
            wzrA.x = fmaf(m0.x, x.x, wzrA.x); wzrA.y = fmaf(m0.y, x.x, wzrA.y);
            wzrA.z = fmaf(m0.z, x.x, wzrA.z); wzrA.w = fmaf(m0.w, x.x, wzrA.w);
            wzrB.x = fmaf(m1.x, x.y, wzrB.x); wzrB.y = fmaf(m1.y, x.y, wzrB.y);
            wzrB.z = fmaf(m1.z, x.y, wzrB.z); wzrB.w = fmaf(m1.w, x.y, wzrB.w);
            float4 mh = Wh4[(k >> 1) * 32 + l];
            whA.x = fmaf(mh.x, x.x, whA.x); whA.y = fmaf(mh.y, x.x, whA.y);
            whB.x = fmaf(mh.z, x.y, whB.x); whB.y = fmaf(mh.w, x.y, whB.y);
        }
        float2 az2 = make_float2(wzrA.x + wzrB.x, wzrA.y + wzrB.y);
        float2 ar2 = make_float2(wzrA.z + wzrB.z, wzrA.w + wzrB.w);
        float2 ah2 = make_float2(whA.x + whB.x, whA.y + whB.y);

        // ---- wait for parent h ----
        float2 p2;
        if (d >= 0) {
            if (l == 0) {
                int cnt = 0;
                while (g_ready[d] == 0)
                    if (((++cnt) & 31) == 0) __nanosleep(64);
            }
            __syncwarp();
            __threadfence();   // acquire: order p load after flag observation
            p2 = __ldcg(reinterpret_cast<const float2*>(g_h + (size_t)d * HD) + l);
        } else {
            p2 = make_float2(0.f, 0.f);
        }
        *reinterpret_cast<float2*>(&p_w[2 * l]) = p2;
        __syncwarp();

        // ---- U z/r matvec ----
        float4 sA = make_float4(az2.x, az2.y, ar2.x, ar2.y);
        float4 sB = make_float4(0.f, 0.f, 0.f, 0.f);
#pragma unroll
        for (int k = 0; k < 64; k += 2) {
            float2 x = *reinterpret_cast<const float2*>(&p_w[k]);
            float4 m0 = Uzr4[k * 32 + l];
            float4 m1 = Uzr4[(k + 1) * 32 + l];
            sA.x = fmaf(m0.x, x.x, sA.x); sA.y = fmaf(m0.y, x.x, sA.y);
            sA.z = fmaf(m0.z, x.x, sA.z); sA.w = fmaf(m0.w, x.x, sA.w);
            sB.x = fmaf(m1.x, x.y, sB.x); sB.y = fmaf(m1.y, x.y, sB.y);
            sB.z = fmaf(m1.z, x.y, sB.z); sB.w = fmaf(m1.w, x.y, sB.w);
        }
        float2 z2, r2;
        z2.x = fminf(fmaxf(0.2f * (sA.x + sB.x) + 0.5f, 0.f), 1.f);
        z2.y = fminf(fmaxf(0.2f * (sA.y + sB.y) + 0.5f, 0.f), 1.f);
        r2.x = fminf(fmaxf(0.2f * (sA.z + sB.z) + 0.5f, 0.f), 1.f);
        r2.y = fminf(fmaxf(0.2f * (sA.w + sB.w) + 0.5f, 0.f), 1.f);
        *reinterpret_cast<float2*>(&pr_w[2 * l]) =
            make_float2(p2.x * r2.x, p2.y * r2.y);
        __syncwarp();

        // ---- Uh matvec ----
        float2 hA = ah2, hB = make_float2(0.f, 0.f);
#pragma unroll
        for (int kp = 0; kp < 32; kp++) {
            float2 x = *reinterpret_cast<const float2*>(&pr_w[2 * kp]);
            float4 m = Uh4[kp * 32 + l];
            hA.x = fmaf(m.x, x.x, hA.x); hA.y = fmaf(m.y, x.x, hA.y);
            hB.x = fmaf(m.z, x.y, hB.x); hB.y = fmaf(m.w, x.y, hB.y);
        }
        float2 h2;
        h2.x = z2.x * p2.x + (1.f - z2.x) * tanhf(hA.x + hB.x);
        h2.y = z2.y * p2.y + (1.f - z2.y) * tanhf(hA.y + hB.y);

        __stcg(reinterpret_cast<float2*>(g_h + (size_t)i * HD) + l, h2);
        if (i >= np1) {
            lm.x = fmaxf(lm.x, h2.x);
            lm.y = fmaxf(lm.y, h2.y);
        }
        __threadfence();          // release h stores
        __syncwarp();
        if (l == 0) g_ready[i] = 1;
    }

    // fold local max, then last block writes output
    unsigned ux = __float_as_uint(lm.x);
    ux = (ux & 0x80000000u) ? ~ux : (ux | 0x80000000u);
    unsigned uy = __float_as_uint(lm.y);
    uy = (uy & 0x80000000u) ? ~uy : (uy | 0x80000000u);
    atomicMax(&g_max[2 * l], ux);
    atomicMax(&g_max[2 * l + 1], uy);
    __threadfence();
    __syncthreads();
    __shared__ unsigned s_last;
    if (tid == 0) s_last = (atomicAdd(&g_done, 1u) == BLKS - 1) ? 1u : 0u;
    __syncthreads();
    if (s_last && tid < HD) {
        unsigned u = atomicMax(&g_max[tid], 0u);   // atomic read of final value
        unsigned b = (u & 0x80000000u) ? (u & 0x7fffffffu) : ~u;
        out[tid] = __uint_as_float(b);
    }
}

// ---------------- launch ----------------
extern "C" void kernel_launch(void* const* d_in, const int* in_sizes, int n_in,
                              void* d_out, int out_size) {
    const float* xw = (const float*)d_in[0];
    const int* xi = (const int*)d_in[1];
    const int* tree = (const int*)d_in[2];
    const int* np = (const int*)d_in[3];
    const float* emb = (const float*)d_in[4];
    const float* Wz = (const float*)d_in[5];
    const float* Uz = (const float*)d_in[6];
    const float* bz = (const float*)d_in[7];
    const float* Wr = (const float*)d_in[8];
    const float* Ur = (const float*)d_in[9];
    const float* br = (const float*)d_in[10];
    const float* Wh = (const float*)d_in[11];
    const float* Uh = (const float*)d_in[12];
    const float* bh = (const float*)d_in[13];

    int N = in_sizes[2] / 2;      // tree is [N,2]
    int L = in_sizes[0] / N;      // x_word is [N,L]
    int n_steps = N - 1;
    int emb_total = in_sizes[4];  // V*H floats

    static int smem_set = 0;
    const int SMEM_BYTES = (24576 + 1536) * 4;  // 104448
    if (!smem_set) {
        cudaFuncSetAttribute(recurB_kernel,
                             cudaFuncAttributeMaxDynamicSharedMemorySize, SMEM_BYTES);
        smem_set = 1;
    }

    int prep_threads = (emb_total + 7) / 8;
    if (prep_threads < MAXN) prep_threads = MAXN;
    prep_kernel<<<(prep_threads + 255) / 256, 256>>>(emb, tree, n_steps, emb_total);
    fill_kernel<<<(n_steps + 255) / 256, 256>>>(tree, n_steps);
    gatherA_kernel<<<(n_steps + WPB - 1) / WPB, 256>>>(xw, xi, L, n_steps);
    recurB_kernel<<<BLKS, 256, SMEM_BYTES>>>(tree, Wz, Uz, bz, Wr, Ur, br,
                                             Wh, Uh, bh, np, n_steps,
                                             (float*)d_out);
}

// round 13
// speedup vs baseline: 1.0537x; 1.0537x over previous
#include <cuda_runtime.h>
#include <cuda_fp16.h>
#include <cstdint>

#define MAXN 8192
#define HD 64
#define SLOTS 32
#define EMB_MAX (50000 * HD)
#define BLKS 296
#define WPB 8

// ---------------- static device scratch ----------------
__device__ __half g_embh[EMB_MAX];
__device__ float g_xe[MAXN * HD];
__device__ float g_h[MAXN * HD];
__device__ int g_wr[MAXN];
__device__ int g_cnt[MAXN];
__device__ int g_buck[MAXN * SLOTS];
__device__ volatile int g_ready[MAXN];
__device__ unsigned g_max[HD];
__device__ unsigned g_done;
__device__ unsigned g_ctr;      // dynamic ticket counter

// ---------------- prep: fp16 embedding conversion + state reset ----------------
__global__ void prep_kernel(const float* __restrict__ emb, const int* __restrict__ tree,
                            int n_steps, int emb_total) {
    int t = blockIdx.x * blockDim.x + threadIdx.x;
    int e = t * 8;
    if (e + 7 < emb_total) {
        float4 f0 = *reinterpret_cast<const float4*>(emb + e);
        float4 f1 = *reinterpret_cast<const float4*>(emb + e + 4);
        *reinterpret_cast<__half2*>(g_embh + e)     = __floats2half2_rn(f0.x, f0.y);
        *reinterpret_cast<__half2*>(g_embh + e + 2) = __floats2half2_rn(f0.z, f0.w);
        *reinterpret_cast<__half2*>(g_embh + e + 4) = __floats2half2_rn(f1.x, f1.y);
        *reinterpret_cast<__half2*>(g_embh + e + 6) = __floats2half2_rn(f1.z, f1.w);
    }
    if (t < n_steps) {
        g_wr[t] = tree[2 * t + 1];
        g_ready[t] = 0;
    }
    if (t < MAXN) g_cnt[t] = 0;
    if (t < HD) g_max[t] = 0u;
    if (t == 0) { g_done = 0u; g_ctr = 0u; }
}

// ---------------- bucket fill: writes per node ----------------
__global__ void fill_kernel(const int* __restrict__ tree, int n_steps) {
    int i = blockIdx.x * blockDim.x + threadIdx.x;
    if (i >= n_steps) return;
    int v = tree[2 * i + 1];
    int s = atomicAdd(&g_cnt[v], 1);
    if (s < SLOTS) g_buck[v * SLOTS + s] = i;
}

// ---------------- kernel A: pure gather at high occupancy (1 warp = 1 step) ----------------
__global__ void __launch_bounds__(256)
gatherA_kernel(const float* __restrict__ xw, const int* __restrict__ xi,
               int L, int n_steps) {
    int wid = threadIdx.x >> 5, l = threadIdx.x & 31;
    int i = blockIdx.x * WPB + wid;
    if (i >= n_steps) return;
    int rl = l & 7, rg = l >> 3;

    float acc[8] = {0.f, 0.f, 0.f, 0.f, 0.f, 0.f, 0.f, 0.f};
    const float* xwr = xw + (size_t)i * L;
    const int* xir = xi + (size_t)i * L;
#pragma unroll 2
    for (int r = 0; r < L; r += 16) {
        int rbase = r + 4 * rg;
        float4 w4 = __ldg(reinterpret_cast<const float4*>(xwr + rbase));
        int4 i4 = __ldg(reinterpret_cast<const int4*>(xir + rbase));
        uint4 u0 = __ldg(reinterpret_cast<const uint4*>(g_embh + (size_t)i4.x * HD + rl * 8));
        uint4 u1 = __ldg(reinterpret_cast<const uint4*>(g_embh + (size_t)i4.y * HD + rl * 8));
        uint4 u2 = __ldg(reinterpret_cast<const uint4*>(g_embh + (size_t)i4.z * HD + rl * 8));
        uint4 u3 = __ldg(reinterpret_cast<const uint4*>(g_embh + (size_t)i4.w * HD + rl * 8));
#define ACCUM(U, W)                                                              \
        {                                                                        \
            float2 f0 = __half22float2(*reinterpret_cast<__half2*>(&U.x));      \
            float2 f1 = __half22float2(*reinterpret_cast<__half2*>(&U.y));      \
            float2 f2 = __half22float2(*reinterpret_cast<__half2*>(&U.z));      \
            float2 f3 = __half22float2(*reinterpret_cast<__half2*>(&U.w));      \
            acc[0] = fmaf(W, f0.x, acc[0]); acc[1] = fmaf(W, f0.y, acc[1]);     \
            acc[2] = fmaf(W, f1.x, acc[2]); acc[3] = fmaf(W, f1.y, acc[3]);     \
            acc[4] = fmaf(W, f2.x, acc[4]); acc[5] = fmaf(W, f2.y, acc[5]);     \
            acc[6] = fmaf(W, f3.x, acc[6]); acc[7] = fmaf(W, f3.y, acc[7]);     \
        }
        ACCUM(u0, w4.x) ACCUM(u1, w4.y) ACCUM(u2, w4.z) ACCUM(u3, w4.w)
#undef ACCUM
    }
#pragma unroll
    for (int u = 0; u < 8; u++) {
        acc[u] += __shfl_xor_sync(0xffffffffu, acc[u], 8);
        acc[u] += __shfl_xor_sync(0xffffffffu, acc[u], 16);
    }
    if (rg == 0) {
        float4 a = make_float4(acc[0], acc[1], acc[2], acc[3]);
        float4 b = make_float4(acc[4], acc[5], acc[6], acc[7]);
        *reinterpret_cast<float4*>(g_xe + (size_t)i * HD + rl * 8) = a;
        *reinterpret_cast<float4*>(g_xe + (size_t)i * HD + rl * 8 + 4) = b;
    }
}

// ---------------- kernel B: GRU recurrence, dynamic ticket dispatch ----------------
__global__ void __launch_bounds__(256, 2)
recurB_kernel(const int* __restrict__ tree,
              const float* __restrict__ Wz, const float* __restrict__ Uz,
              const float* __restrict__ bz,
              const float* __restrict__ Wr, const float* __restrict__ Ur,
              const float* __restrict__ br,
              const float* __restrict__ Wh, const float* __restrict__ Uh,
              const float* __restrict__ bh,
              const int* __restrict__ np_ptr, int n_steps,
              float* __restrict__ out) {
    extern __shared__ float sm[];
    float* sWzr = sm;             // [k*128 + 4l + {Wz2l,Wz2l+1,Wr2l,Wr2l+1}]
    float* sWh2 = sm + 8192;
    float* sUzr = sm + 12288;
    float* sUh2 = sm + 20480;
    float* sXe = sm + 24576;      // per-warp 64
    float* sP  = sm + 25088;
    float* sPr = sm + 25600;

    int tid = threadIdx.x;
    int wid = tid >> 5, l = tid & 31;

    for (int t = tid; t < 8192; t += 256) {
        int k = t >> 7, q = t & 127, lane = q >> 2, c = q & 3;
        int j = 2 * lane + (c & 1);
        sWzr[t] = (c < 2 ? Wz : Wr)[j * 64 + k];
        sUzr[t] = (c < 2 ? Uz : Ur)[j * 64 + k];
    }
    for (int t = tid; t < 4096; t += 256) {
        int kp = t >> 7, q = t & 127, lane = q >> 2, c = q & 3;
        int j = 2 * lane + (c & 1);
        int k = 2 * kp + (c >> 1);
        sWh2[t] = Wh[j * 64 + k];
        sUh2[t] = Uh[j * 64 + k];
    }
    float2 bz2 = reinterpret_cast<const float2*>(bz)[l];
    float2 br2 = reinterpret_cast<const float2*>(br)[l];
    float2 bh2 = reinterpret_cast<const float2*>(bh)[l];
    int np1 = np_ptr[0] - 1;
    __syncthreads();

    const float4* Wzr4 = reinterpret_cast<const float4*>(sWzr);
    const float4* Wh4  = reinterpret_cast<const float4*>(sWh2);
    const float4* Uzr4 = reinterpret_cast<const float4*>(sUzr);
    const float4* Uh4  = reinterpret_cast<const float4*>(sUh2);
    float* xe_w = sXe + wid * 64;
    float* p_w  = sP + wid * 64;
    float* pr_w = sPr + wid * 64;
    float2 lm = make_float2(-3.402823466e38f, -3.402823466e38f);

    for (;;) {
        // ---- dynamic ticket: pop next step index ----
        int i = 0;
        if (l == 0) i = (int)atomicAdd(&g_ctr, 1u);
        i = __shfl_sync(0xffffffffu, i, 0);
        if (i >= n_steps) break;

        // ---- load xe (computed by kernel A) ----
        float2 xe2 = __ldg(reinterpret_cast<const float2*>(g_xe + (size_t)i * HD) + l);
        *reinterpret_cast<float2*>(&xe_w[2 * l]) = xe2;
        __syncwarp();

        // ---- dep(i): last j<i writing node tree[i,0] ----
        int v = tree[2 * i];
        int c = g_cnt[v];
        int d = -1;
        if (c <= SLOTS) {
            if (l < c) {
                int j = g_buck[v * SLOTS + l];
                if (j < i) d = j;
            }
        } else {
            if (l == 0)
                for (int j = i - 1; j >= 0; --j)
                    if (g_wr[j] == v) { d = j; break; }
        }
        d = __reduce_max_sync(0xffffffffu, d);

        // ---- W matvecs (pre-wait): a = W xe + b ----
        float4 wzrA = make_float4(bz2.x, bz2.y, br2.x, br2.y);
        float4 wzrB = make_float4(0.f, 0.f, 0.f, 0.f);
        float2 whA = bh2, whB = make_float2(0.f, 0.f);
#pragma unroll
        for (int k = 0; k < 64; k += 2) {
            float2 x = *reinterpret_cast<const float2*>(&xe_w[k]);
            float4 m0 = Wzr4[k * 32 + l];
            float4 m1 = Wzr4[(k + 1) * 32 + l];
            wzrA.x = fmaf(m0.x, x.x, wzrA.x); wzrA.y = fmaf(m0.y, x.x, wzrA.y);
            wzrA.z = fmaf(m0.z, x.x, wzrA.z); wzrA.w = fmaf(m0.w, x.x, wzrA.w);
            wzrB.x = fmaf(m1.x, x.y, wzrB.x); wzrB.y = fmaf(m1.y, x.y, wzrB.y);
            wzrB.z = fmaf(m1.z, x.y, wzrB.z); wzrB.w = fmaf(m1.w, x.y, wzrB.w);
            float4 mh = Wh4[(k >> 1) * 32 + l];
            whA.x = fmaf(mh.x, x.x, whA.x); whA.y = fmaf(mh.y, x.x, whA.y);
            whB.x = fmaf(mh.z, x.y, whB.x); whB.y = fmaf(mh.w, x.y, whB.y);
        }
        float2 az2 = make_float2(wzrA.x + wzrB.x, wzrA.y + wzrB.y);
        float2 ar2 = make_float2(wzrA.z + wzrB.z, wzrA.w + wzrB.w);
        float2 ah2 = make_float2(whA.x + whB.x, whA.y + whB.y);

        // ---- wait for parent h (busy poll: nanosleep granularity hurts tail links) ----
        float2 p2;
        if (d >= 0) {
            if (l == 0) {
                while (g_ready[d] == 0) { }
            }
            __syncwarp();
            __threadfence();   // acquire: order p load after flag observation
            p2 = __ldcg(reinterpret_cast<const float2*>(g_h + (size_t)d * HD) + l);
        } else {
            p2 = make_float2(0.f, 0.f);
        }
        *reinterpret_cast<float2*>(&p_w[2 * l]) = p2;
        __syncwarp();

        // ---- U z/r matvec ----
        float4 sA = make_float4(az2.x, az2.y, ar2.x, ar2.y);
        float4 sB = make_float4(0.f, 0.f, 0.f, 0.f);
#pragma unroll
        for (int k = 0; k < 64; k += 2) {
            float2 x = *reinterpret_cast<const float2*>(&p_w[k]);
            float4 m0 = Uzr4[k * 32 + l];
            float4 m1 = Uzr4[(k + 1) * 32 + l];
            sA.x = fmaf(m0.x, x.x, sA.x); sA.y = fmaf(m0.y, x.x, sA.y);
            sA.z = fmaf(m0.z, x.x, sA.z); sA.w = fmaf(m0.w, x.x, sA.w);
            sB.x = fmaf(m1.x, x.y, sB.x); sB.y = fmaf(m1.y, x.y, sB.y);
            sB.z = fmaf(m1.z, x.y, sB.z); sB.w = fmaf(m1.w, x.y, sB.w);
        }
        float2 z2, r2;
        z2.x = fminf(fmaxf(0.2f * (sA.x + sB.x) + 0.5f, 0.f), 1.f);
        z2.y = fminf(fmaxf(0.2f * (sA.y + sB.y) + 0.5f, 0.f), 1.f);
        r2.x = fminf(fmaxf(0.2f * (sA.z + sB.z) + 0.5f, 0.f), 1.f);
        r2.y = fminf(fmaxf(0.2f * (sA.w + sB.w) + 0.5f, 0.f), 1.f);
        *reinterpret_cast<float2*>(&pr_w[2 * l]) =
            make_float2(p2.x * r2.x, p2.y * r2.y);
        __syncwarp();

        // ---- Uh matvec ----
        float2 hA = ah2, hB = make_float2(0.f, 0.f);
#pragma unroll
        for (int kp = 0; kp < 32; kp++) {
            float2 x = *reinterpret_cast<const float2*>(&pr_w[2 * kp]);
            float4 m = Uh4[kp * 32 + l];
            hA.x = fmaf(m.x, x.x, hA.x); hA.y = fmaf(m.y, x.x, hA.y);
            hB.x = fmaf(m.z, x.y, hB.x); hB.y = fmaf(m.w, x.y, hB.y);
        }
        float2 h2;
        h2.x = z2.x * p2.x + (1.f - z2.x) * tanhf(hA.x + hB.x);
        h2.y = z2.y * p2.y + (1.f - z2.y) * tanhf(hA.y + hB.y);

        __stcg(reinterpret_cast<float2*>(g_h + (size_t)i * HD) + l, h2);
        if (i >= np1) {
            lm.x = fmaxf(lm.x, h2.x);
            lm.y = fmaxf(lm.y, h2.y);
        }
        __threadfence();          // release h stores
        __syncwarp();
        if (l == 0) g_ready[i] = 1;
    }

    // fold local max, then last block writes output
    unsigned ux = __float_as_uint(lm.x);
    ux = (ux & 0x80000000u) ? ~ux : (ux | 0x80000000u);
    unsigned uy = __float_as_uint(lm.y);
    uy = (uy & 0x80000000u) ? ~uy : (uy | 0x80000000u);
    atomicMax(&g_max[2 * l], ux);
    atomicMax(&g_max[2 * l + 1], uy);
    __threadfence();
    __syncthreads();
    __shared__ unsigned s_last;
    if (tid == 0) s_last = (atomicAdd(&g_done, 1u) == BLKS - 1) ? 1u : 0u;
    __syncthreads();
    if (s_last && tid < HD) {
        unsigned u = atomicMax(&g_max[tid], 0u);   // atomic read of final value
        unsigned b = (u & 0x80000000u) ? (u & 0x7fffffffu) : ~u;
        out[tid] = __uint_as_float(b);
    }
}

// ---------------- launch ----------------
extern "C" void kernel_launch(void* const* d_in, const int* in_sizes, int n_in,
                              void* d_out, int out_size) {
    const float* xw = (const float*)d_in[0];
    const int* xi = (const int*)d_in[1];
    const int* tree = (const int*)d_in[2];
    const int* np = (const int*)d_in[3];
    const float* emb = (const float*)d_in[4];
    const float* Wz = (const float*)d_in[5];
    const float* Uz = (const float*)d_in[6];
    const float* bz = (const float*)d_in[7];
    const float* Wr = (const float*)d_in[8];
    const float* Ur = (const float*)d_in[9];
    const float* br = (const float*)d_in[10];
    const float* Wh = (const float*)d_in[11];
    const float* Uh = (const float*)d_in[12];
    const float* bh = (const float*)d_in[13];

    int N = in_sizes[2] / 2;      // tree is [N,2]
    int L = in_sizes[0] / N;      // x_word is [N,L]
    int n_steps = N - 1;
    int emb_total = in_sizes[4];  // V*H floats

    static int smem_set = 0;
    const int SMEM_BYTES = (24576 + 1536) * 4;  // 104448
    if (!smem_set) {
        cudaFuncSetAttribute(recurB_kernel,
                             cudaFuncAttributeMaxDynamicSharedMemorySize, SMEM_BYTES);
        smem_set = 1;
    }

    int prep_threads = (emb_total + 7) / 8;
    if (prep_threads < MAXN) prep_threads = MAXN;
    prep_kernel<<<(prep_threads + 255) / 256, 256>>>(emb, tree, n_steps, emb_total);
    fill_kernel<<<(n_steps + 255) / 256, 256>>>(tree, n_steps);
    gatherA_kernel<<<(n_steps + WPB - 1) / WPB, 256>>>(xw, xi, L, n_steps);
    recurB_kernel<<<BLKS, 256, SMEM_BYTES>>>(tree, Wz, Uz, bz, Wr, Ur, br,
                                             Wh, Uh, bh, np, n_steps,
                                             (float*)d_out);
}

// round 14
// speedup vs baseline: 1.1968x; 1.1358x over previous
#include <cuda_runtime.h>
#include <cuda_fp16.h>
#include <cstdint>

#define MAXN 8192
#define HD 64
#define SLOTS 32
#define EMB_MAX (50000 * HD)
#define BLKS 296
#define WPB 8
#define TW (BLKS * WPB)
#define GCH 128   // gather chunk rows

// ---------------- static device scratch ----------------
__device__ __half g_embh[EMB_MAX];
__device__ float g_h[MAXN * HD];
__device__ int g_wr[MAXN];
__device__ int g_cnt[MAXN];
__device__ int g_buck[MAXN * SLOTS];
__device__ volatile int g_ready[MAXN];
__device__ unsigned g_max[HD];
__device__ unsigned g_done;

// ---------------- prep: fp16 embedding conversion + state reset ----------------
__global__ void prep_kernel(const float* __restrict__ emb, const int* __restrict__ tree,
                            int n_steps, int emb_total) {
    int t = blockIdx.x * blockDim.x + threadIdx.x;
    int e = t * 8;
    if (e + 7 < emb_total) {
        float4 f0 = *reinterpret_cast<const float4*>(emb + e);
        float4 f1 = *reinterpret_cast<const float4*>(emb + e + 4);
        *reinterpret_cast<__half2*>(g_embh + e)     = __floats2half2_rn(f0.x, f0.y);
        *reinterpret_cast<__half2*>(g_embh + e + 2) = __floats2half2_rn(f0.z, f0.w);
        *reinterpret_cast<__half2*>(g_embh + e + 4) = __floats2half2_rn(f1.x, f1.y);
        *reinterpret_cast<__half2*>(g_embh + e + 6) = __floats2half2_rn(f1.z, f1.w);
    }
    if (t < n_steps) {
        g_wr[t] = tree[2 * t + 1];
        g_ready[t] = 0;
    }
    if (t < MAXN) g_cnt[t] = 0;
    if (t < HD) g_max[t] = 0u;
    if (t == 0) g_done = 0u;
}

// ---------------- bucket fill: writes per node ----------------
__global__ void fill_kernel(const int* __restrict__ tree, int n_steps) {
    int i = blockIdx.x * blockDim.x + threadIdx.x;
    if (i >= n_steps) return;
    int v = tree[2 * i + 1];
    int s = atomicAdd(&g_cnt[v], 1);
    if (s < SLOTS) g_buck[v * SLOTS + s] = i;
}

// ---------------- gather one 128-row chunk ----------------
__device__ __forceinline__ void gather_chunk(const float* __restrict__ xwr,
                                             const int* __restrict__ xir,
                                             int r0, int rl, int rg, float acc[8]) {
#pragma unroll 2
    for (int rr = 0; rr < GCH; rr += 16) {
        int rbase = r0 + rr + 4 * rg;
        float4 w4 = __ldg(reinterpret_cast<const float4*>(xwr + rbase));
        int4 i4 = __ldg(reinterpret_cast<const int4*>(xir + rbase));
        uint4 u0 = __ldg(reinterpret_cast<const uint4*>(g_embh + (size_t)i4.x * HD + rl * 8));
        uint4 u1 = __ldg(reinterpret_cast<const uint4*>(g_embh + (size_t)i4.y * HD + rl * 8));
        uint4 u2 = __ldg(reinterpret_cast<const uint4*>(g_embh + (size_t)i4.z * HD + rl * 8));
        uint4 u3 = __ldg(reinterpret_cast<const uint4*>(g_embh + (size_t)i4.w * HD + rl * 8));
#define ACCUM(U, W)                                                              \
        {                                                                        \
            float2 f0 = __half22float2(*reinterpret_cast<__half2*>(&U.x));      \
            float2 f1 = __half22float2(*reinterpret_cast<__half2*>(&U.y));      \
            float2 f2 = __half22float2(*reinterpret_cast<__half2*>(&U.z));      \
            float2 f3 = __half22float2(*reinterpret_cast<__half2*>(&U.w));      \
            acc[0] = fmaf(W, f0.x, acc[0]); acc[1] = fmaf(W, f0.y, acc[1]);     \
            acc[2] = fmaf(W, f1.x, acc[2]); acc[3] = fmaf(W, f1.y, acc[3]);     \
            acc[4] = fmaf(W, f2.x, acc[4]); acc[5] = fmaf(W, f2.y, acc[5]);     \
            acc[6] = fmaf(W, f3.x, acc[6]); acc[7] = fmaf(W, f3.y, acc[7]);     \
        }
        ACCUM(u0, w4.x) ACCUM(u1, w4.y) ACCUM(u2, w4.z) ACCUM(u3, w4.w)
#undef ACCUM
    }
}

// convert a packed half2 (held in a 32-bit lane of uint4/uint2) to float2
#define CVT2(dst, h) { __half2 _hh = *reinterpret_cast<const __half2*>(&(h)); dst = __half22float2(_hh); }

// one k-pair of the Wz/Wr/Wh matvec (fp16 weights)
#define W_STEP(KP, AZR, AH) do {                                                     \
    float2 x = *reinterpret_cast<const float2*>(&xe_w[2 * (KP)]);                    \
    uint4 u = sWzr[(KP) * 32 + l];                                                   \
    uint2 v2 = sWh[(KP) * 32 + l];                                                   \
    float2 f;                                                                        \
    CVT2(f, u.x);  AZR.x = fmaf(f.x, x.x, AZR.x); AZR.x = fmaf(f.y, x.y, AZR.x);     \
    CVT2(f, u.y);  AZR.y = fmaf(f.x, x.x, AZR.y); AZR.y = fmaf(f.y, x.y, AZR.y);     \
    CVT2(f, u.z);  AZR.z = fmaf(f.x, x.x, AZR.z); AZR.z = fmaf(f.y, x.y, AZR.z);     \
    CVT2(f, u.w);  AZR.w = fmaf(f.x, x.x, AZR.w); AZR.w = fmaf(f.y, x.y, AZR.w);     \
    CVT2(f, v2.x); AH.x  = fmaf(f.x, x.x, AH.x);  AH.x  = fmaf(f.y, x.y, AH.x);      \
    CVT2(f, v2.y); AH.y  = fmaf(f.x, x.x, AH.y);  AH.y  = fmaf(f.y, x.y, AH.y);      \
} while (0)

// one k-pair of the Uz/Ur matvec (fp16 weights)
#define UZR_STEP(KP, S) do {                                                         \
    float2 x = *reinterpret_cast<const float2*>(&p_w[2 * (KP)]);                     \
    uint4 u = sUzr[(KP) * 32 + l];                                                   \
    float2 f;                                                                        \
    CVT2(f, u.x); S.x = fmaf(f.x, x.x, S.x); S.x = fmaf(f.y, x.y, S.x);              \
    CVT2(f, u.y); S.y = fmaf(f.x, x.x, S.y); S.y = fmaf(f.y, x.y, S.y);              \
    CVT2(f, u.z); S.z = fmaf(f.x, x.x, S.z); S.z = fmaf(f.y, x.y, S.z);              \
    CVT2(f, u.w); S.w = fmaf(f.x, x.x, S.w); S.w = fmaf(f.y, x.y, S.w);              \
} while (0)

// one k-pair of the Uh matvec (fp16 weights)
#define UH_STEP(KP, HACC) do {                                                       \
    float2 x = *reinterpret_cast<const float2*>(&pr_w[2 * (KP)]);                    \
    uint2 v2 = sUh[(KP) * 32 + l];                                                   \
    float2 f;                                                                        \
    CVT2(f, v2.x); HACC.x = fmaf(f.x, x.x, HACC.x); HACC.x = fmaf(f.y, x.y, HACC.x); \
    CVT2(f, v2.y); HACC.y = fmaf(f.x, x.x, HACC.y); HACC.y = fmaf(f.y, x.y, HACC.y); \
} while (0)

// ---------------- fused gather + GRU dataflow (one step per warp, pipelined) ----------------
__global__ void __launch_bounds__(256, 2)
fused_kernel(const float* __restrict__ xw, const int* __restrict__ xi,
             const int* __restrict__ tree,
             const float* __restrict__ Wz, const float* __restrict__ Uz,
             const float* __restrict__ bz,
             const float* __restrict__ Wr, const float* __restrict__ Ur,
             const float* __restrict__ br,
             const float* __restrict__ Wh, const float* __restrict__ Uh,
             const float* __restrict__ bh,
             const int* __restrict__ np_ptr, int L, int n_steps,
             float* __restrict__ out) {
    extern __shared__ char smc[];
    // fp16 weight tiles, packed half2-along-k:
    // sWzr[kp*32+l] = {Wz[2l][2kp..2kp+1], Wz[2l+1][...], Wr[2l][...], Wr[2l+1][...]}
    uint4* sWzr = reinterpret_cast<uint4*>(smc);                // 16384 B
    uint2* sWh  = reinterpret_cast<uint2*>(smc + 16384);        //  8192 B
    uint4* sUzr = reinterpret_cast<uint4*>(smc + 24576);        // 16384 B
    uint2* sUh  = reinterpret_cast<uint2*>(smc + 40960);        //  8192 B
    float* sXe  = reinterpret_cast<float*>(smc + 49152);        //  2048 B (8 warps x 64)
    float* sP   = reinterpret_cast<float*>(smc + 51200);        //  2048 B
    float* sPr  = reinterpret_cast<float*>(smc + 53248);        //  2048 B

    int tid = threadIdx.x;
    int wid = tid >> 5, l = tid & 31;
    int rl = l & 7, rg = l >> 3;

    // pack all six 64x64 weight matrices into fp16 smem tiles
    for (int t = tid; t < 1024; t += 256) {
        int kp = t >> 5, ln = t & 31;
        int j0 = 2 * ln, k0 = 2 * kp;
        __half2 h;
        uint4 u;
        h = __floats2half2_rn(Wz[j0 * 64 + k0], Wz[j0 * 64 + k0 + 1]);        u.x = *reinterpret_cast<unsigned*>(&h);
        h = __floats2half2_rn(Wz[(j0 + 1) * 64 + k0], Wz[(j0 + 1) * 64 + k0 + 1]); u.y = *reinterpret_cast<unsigned*>(&h);
        h = __floats2half2_rn(Wr[j0 * 64 + k0], Wr[j0 * 64 + k0 + 1]);        u.z = *reinterpret_cast<unsigned*>(&h);
        h = __floats2half2_rn(Wr[(j0 + 1) * 64 + k0], Wr[(j0 + 1) * 64 + k0 + 1]); u.w = *reinterpret_cast<unsigned*>(&h);
        sWzr[t] = u;
        h = __floats2half2_rn(Uz[j0 * 64 + k0], Uz[j0 * 64 + k0 + 1]);        u.x = *reinterpret_cast<unsigned*>(&h);
        h = __floats2half2_rn(Uz[(j0 + 1) * 64 + k0], Uz[(j0 + 1) * 64 + k0 + 1]); u.y = *reinterpret_cast<unsigned*>(&h);
        h = __floats2half2_rn(Ur[j0 * 64 + k0], Ur[j0 * 64 + k0 + 1]);        u.z = *reinterpret_cast<unsigned*>(&h);
        h = __floats2half2_rn(Ur[(j0 + 1) * 64 + k0], Ur[(j0 + 1) * 64 + k0 + 1]); u.w = *reinterpret_cast<unsigned*>(&h);
        sUzr[t] = u;
        uint2 v2;
        h = __floats2half2_rn(Wh[j0 * 64 + k0], Wh[j0 * 64 + k0 + 1]);        v2.x = *reinterpret_cast<unsigned*>(&h);
        h = __floats2half2_rn(Wh[(j0 + 1) * 64 + k0], Wh[(j0 + 1) * 64 + k0 + 1]); v2.y = *reinterpret_cast<unsigned*>(&h);
        sWh[t] = v2;
        h = __floats2half2_rn(Uh[j0 * 64 + k0], Uh[j0 * 64 + k0 + 1]);        v2.x = *reinterpret_cast<unsigned*>(&h);
        h = __floats2half2_rn(Uh[(j0 + 1) * 64 + k0], Uh[(j0 + 1) * 64 + k0 + 1]); v2.y = *reinterpret_cast<unsigned*>(&h);
        sUh[t] = v2;
    }
    float2 bz2 = reinterpret_cast<const float2*>(bz)[l];
    float2 br2 = reinterpret_cast<const float2*>(br)[l];
    float2 bh2 = reinterpret_cast<const float2*>(bh)[l];
    int np1 = np_ptr[0] - 1;
    __syncthreads();

    float* xe_w = sXe + wid * 64;
    float* p_w  = sP + wid * 64;
    float* pr_w = sPr + wid * 64;
    float2 lm = make_float2(-3.402823466e38f, -3.402823466e38f);

    // preamble: gather first owned step
    int i0 = blockIdx.x * WPB + wid;
    float acc[8] = {0.f, 0.f, 0.f, 0.f, 0.f, 0.f, 0.f, 0.f};
    if (i0 < n_steps) {
        const float* xwr = xw + (size_t)i0 * L;
        const int* xir = xi + (size_t)i0 * L;
        for (int r0 = 0; r0 < L; r0 += GCH) gather_chunk(xwr, xir, r0, rl, rg, acc);
    }

    for (int i = i0; i < n_steps; i += TW) {
        int inext = i + TW;
        bool has_next = (inext < n_steps);
        const float* xwrN = xw + (size_t)inext * L;
        const int* xirN = xi + (size_t)inext * L;

        // ---- reduce acc -> xe_w (sum over rg groups) ----
#pragma unroll
        for (int u = 0; u < 8; u++) {
            acc[u] += __shfl_xor_sync(0xffffffffu, acc[u], 8);
            acc[u] += __shfl_xor_sync(0xffffffffu, acc[u], 16);
        }
        if (rg == 0) {
#pragma unroll
            for (int u = 0; u < 8; u++) xe_w[rl * 8 + u] = acc[u];
        }
        __syncwarp();
#pragma unroll
        for (int u = 0; u < 8; u++) acc[u] = 0.f;

        // ---- dep(i): last j<i writing node tree[i,0] ----
        int v = tree[2 * i];
        int c = g_cnt[v];
        int d = -1;
        if (c <= SLOTS) {
            if (l < c) {
                int j = g_buck[v * SLOTS + l];
                if (j < i) d = j;
            }
        } else {
            if (l == 0)
                for (int j = i - 1; j >= 0; --j)
                    if (g_wr[j] == v) { d = j; break; }
        }
        d = __reduce_max_sync(0xffffffffu, d);

        // ---- W matvecs (pre-wait): a = W xe + b  (fp16 weights) ----
        float4 azr0 = make_float4(bz2.x, bz2.y, br2.x, br2.y);
        float4 azr1 = make_float4(0.f, 0.f, 0.f, 0.f);
        float2 ah0 = bh2, ah1 = make_float2(0.f, 0.f);
#pragma unroll
        for (int kp = 0; kp < 32; kp += 2) {
            W_STEP(kp, azr0, ah0);
            W_STEP(kp + 1, azr1, ah1);
        }
        float2 az2 = make_float2(azr0.x + azr1.x, azr0.y + azr1.y);
        float2 ar2 = make_float2(azr0.z + azr1.z, azr0.w + azr1.w);
        float2 ah2 = make_float2(ah0.x + ah1.x, ah0.y + ah1.y);

        // ---- probe dep; gather next step's chunks while not ready ----
        int pr_r0 = 0;
        float2 p2;
        if (d >= 0) {
            int rdy = (l == 0) ? g_ready[d] : 0;
            rdy = __shfl_sync(0xffffffffu, rdy, 0);
            while (!rdy) {
                if (has_next && pr_r0 < L) {
                    gather_chunk(xwrN, xirN, pr_r0, rl, rg, acc);
                    pr_r0 += GCH;
                } else {
                    if (l == 0) {
                        int cnt = 0;
                        while (g_ready[d] == 0)
                            if (((++cnt) & 31) == 0) __nanosleep(64);
                    }
                    break;
                }
                rdy = (l == 0) ? g_ready[d] : 0;
                rdy = __shfl_sync(0xffffffffu, rdy, 0);
            }
            __syncwarp();
            __threadfence();   // acquire: order p load after flag observation
            p2 = __ldcg(reinterpret_cast<const float2*>(g_h + (size_t)d * HD) + l);
        } else {
            p2 = make_float2(0.f, 0.f);
        }
        *reinterpret_cast<float2*>(&p_w[2 * l]) = p2;
        __syncwarp();

        // ---- U z/r matvec (fp16 weights) ----
        float4 s0 = make_float4(az2.x, az2.y, ar2.x, ar2.y);
        float4 s1 = make_float4(0.f, 0.f, 0.f, 0.f);
#pragma unroll
        for (int kp = 0; kp < 32; kp += 2) {
            UZR_STEP(kp, s0);
            UZR_STEP(kp + 1, s1);
        }
        float2 z2, r2;
        z2.x = fminf(fmaxf(0.2f * (s0.x + s1.x) + 0.5f, 0.f), 1.f);
        z2.y = fminf(fmaxf(0.2f * (s0.y + s1.y) + 0.5f, 0.f), 1.f);
        r2.x = fminf(fmaxf(0.2f * (s0.z + s1.z) + 0.5f, 0.f), 1.f);
        r2.y = fminf(fmaxf(0.2f * (s0.w + s1.w) + 0.5f, 0.f), 1.f);
        *reinterpret_cast<float2*>(&pr_w[2 * l]) =
            make_float2(p2.x * r2.x, p2.y * r2.y);
        __syncwarp();

        // ---- Uh matvec (fp16 weights) ----
        float2 h0 = ah2, h1 = make_float2(0.f, 0.f);
#pragma unroll
        for (int kp = 0; kp < 32; kp += 2) {
            UH_STEP(kp, h0);
            UH_STEP(kp + 1, h1);
        }
        float2 h2;
        h2.x = z2.x * p2.x + (1.f - z2.x) * tanhf(h0.x + h1.x);
        h2.y = z2.y * p2.y + (1.f - z2.y) * tanhf(h0.y + h1.y);

        __stcg(reinterpret_cast<float2*>(g_h + (size_t)i * HD) + l, h2);
        if (i >= np1) {
            lm.x = fmaxf(lm.x, h2.x);
            lm.y = fmaxf(lm.y, h2.y);
        }
        __threadfence();          // release h stores
        __syncwarp();
        if (l == 0) g_ready[i] = 1;

        // ---- finish remaining gather chunks for next step ----
        while (has_next && pr_r0 < L) {
            gather_chunk(xwrN, xirN, pr_r0, rl, rg, acc);
            pr_r0 += GCH;
        }
    }

    // fold local max, then last block writes output
    unsigned ux = __float_as_uint(lm.x);
    ux = (ux & 0x80000000u) ? ~ux : (ux | 0x80000000u);
    unsigned uy = __float_as_uint(lm.y);
    uy = (uy & 0x80000000u) ? ~uy : (uy | 0x80000000u);
    atomicMax(&g_max[2 * l], ux);
    atomicMax(&g_max[2 * l + 1], uy);
    __threadfence();
    __syncthreads();
    __shared__ unsigned s_last;
    if (tid == 0) s_last = (atomicAdd(&g_done, 1u) == BLKS - 1) ? 1u : 0u;
    __syncthreads();
    if (s_last && tid < HD) {
        unsigned u = atomicMax(&g_max[tid], 0u);   // atomic read of final value
        unsigned b = (u & 0x80000000u) ? (u & 0x7fffffffu) : ~u;
        out[tid] = __uint_as_float(b);
    }
}

// ---------------- launch ----------------
extern "C" void kernel_launch(void* const* d_in, const int* in_sizes, int n_in,
                              void* d_out, int out_size) {
    const float* xw = (const float*)d_in[0];
    const int* xi = (const int*)d_in[1];
    const int* tree = (const int*)d_in[2];
    const int* np = (const int*)d_in[3];
    const float* emb = (const float*)d_in[4];
    const float* Wz = (const float*)d_in[5];
    const float* Uz = (const float*)d_in[6];
    const float* bz = (const float*)d_in[7];
    const float* Wr = (const float*)d_in[8];
    const float* Ur = (const float*)d_in[9];
    const float* br = (const float*)d_in[10];
    const float* Wh = (const float*)d_in[11];
    const float* Uh = (const float*)d_in[12];
    const float* bh = (const float*)d_in[13];

    int N = in_sizes[2] / 2;      // tree is [N,2]
    int L = in_sizes[0] / N;      // x_word is [N,L]
    int n_steps = N - 1;
    int emb_total = in_sizes[4];  // V*H floats

    static int smem_set = 0;
    const int SMEM_BYTES = 55296;   // 48K fp16 weights + 6K warp buffers
    if (!smem_set) {
        cudaFuncSetAttribute(fused_kernel,
                             cudaFuncAttributeMaxDynamicSharedMemorySize, SMEM_BYTES);
        smem_set = 1;
    }

    int prep_threads = (emb_total + 7) / 8;
    if (prep_threads < MAXN) prep_threads = MAXN;
    prep_kernel<<<(prep_threads + 255) / 256, 256>>>(emb, tree, n_steps, emb_total);
    fill_kernel<<<(n_steps + 255) / 256, 256>>>(tree, n_steps);
    fused_kernel<<<BLKS, 256, SMEM_BYTES>>>(xw, xi, tree, Wz, Uz, bz, Wr, Ur, br,
                                            Wh, Uh, bh, np, L, n_steps,
                                            (float*)d_out);
}